// round 12
// baseline (speedup 1.0000x reference)
#include <cuda_runtime.h>
#include <cuda_bf16.h>
#include <cuda_fp16.h>
#include <math.h>
#include <stdint.h>

#define NN 50000
#define EE 400000
#define D_IN 128
#define D_HID 128
#define D_OUT 64

// ---------------- scratch ----------------
__device__ float g_Q0[4][NN * D_HID];
__device__ __half g_K0[4][NN * D_HID];
__device__ __half g_V0[4][NN * D_HID];
__device__ float g_H[NN * D_HID];
__device__ float g_Q1[2][NN * D_OUT];
__device__ __half g_K1[2][NN * D_OUT];
__device__ __half g_V1[2][NN * D_OUT];
__device__ int g_deg[2][NN];
__device__ int g_scan[2][NN];
__device__ int g_bsum[2][256];
__device__ int g_boff[2][256];
__device__ int g_cursor[2][NN];
__device__ int g_rowptr[2][NN + 1];
__device__ int g_cols[2][EE];

// split-bf16 operands (hi + lo), weights stored transposed [n][k]
__device__ __nv_bfloat16 g_Xh[NN * D_IN], g_Xl[NN * D_IN];
__device__ __nv_bfloat16 g_Hh[NN * D_HID], g_Hl[NN * D_HID];
__device__ __nv_bfloat16 g_W0h[12][D_HID * D_IN], g_W0l[12][D_HID * D_IN];
__device__ __nv_bfloat16 g_W1h[6][D_OUT * D_HID], g_W1l[6][D_OUT * D_HID];

__device__ __forceinline__ void split_bf16(float v, __nv_bfloat16& h, __nv_bfloat16& l) {
    h = __float2bfloat16(v);
    l = __float2bfloat16(v - __bfloat162float(h));
}

// ---------------- CSR build ----------------
__global__ void zero2_kernel(int n) {
    int i = blockIdx.x * blockDim.x + threadIdx.x;
    if (i < n) g_deg[blockIdx.y][i] = 0;
}

__global__ void count2_kernel(const int* __restrict__ e0, const int* __restrict__ e1, int e) {
    int i = blockIdx.x * blockDim.x + threadIdx.x;
    int hop = blockIdx.y;
    const int* rows = hop ? e1 : e0;
    if (i < e) atomicAdd(&g_deg[hop][rows[i]], 1);
}

__global__ void scanA_kernel(int n) {
    int hop = blockIdx.y;
    int chunk = blockIdx.x;
    int tid = threadIdx.x;
    int i = chunk * 256 + tid;
    int v = (i < n) ? g_deg[hop][i] : 0;
    __shared__ int sm[256];
    sm[tid] = v;
    __syncthreads();
#pragma unroll
    for (int off = 1; off < 256; off <<= 1) {
        int t = (tid >= off) ? sm[tid - off] : 0;
        __syncthreads();
        sm[tid] += t;
        __syncthreads();
    }
    if (i < n) g_scan[hop][i] = sm[tid] - v;
    if (tid == 255) g_bsum[hop][chunk] = sm[255];
}

__global__ void scanB_kernel(int nblk) {
    __shared__ int sm[256];
    int tid = threadIdx.x;
    for (int hop = 0; hop < 2; hop++) {
        int v = (tid < nblk) ? g_bsum[hop][tid] : 0;
        sm[tid] = v;
        __syncthreads();
#pragma unroll
        for (int off = 1; off < 256; off <<= 1) {
            int t = (tid >= off) ? sm[tid - off] : 0;
            __syncthreads();
            sm[tid] += t;
            __syncthreads();
        }
        if (tid < nblk) g_boff[hop][tid] = sm[tid] - v;
        __syncthreads();
    }
}

__global__ void scanC_kernel(int n, int e) {
    int i = blockIdx.x * blockDim.x + threadIdx.x;
    int hop = blockIdx.y;
    if (i < n) {
        int rp = g_scan[hop][i] + g_boff[hop][i >> 8];
        g_rowptr[hop][i] = rp;
        g_cursor[hop][i] = rp;
        if (i == 0) g_rowptr[hop][n] = e;
    }
}

__global__ void scatter2_kernel(const int* __restrict__ e0, const int* __restrict__ e1, int e) {
    int i = blockIdx.x * blockDim.x + threadIdx.x;
    int hop = blockIdx.y;
    const int* rows = hop ? e1 : e0;
    if (i < e) {
        int r = rows[i];
        int c = rows[i + e];
        int p = atomicAdd(&g_cursor[hop][r], 1);
        g_cols[hop][p] = c;
    }
}

// ---------------- split precompute ----------------
__global__ void split_x_kernel(const float* __restrict__ x, int n) {
    int i = blockIdx.x * blockDim.x + threadIdx.x;
    if (i < n) split_bf16(x[i], g_Xh[i], g_Xl[i]);
}

__global__ void split_w_kernel(
    const float* __restrict__ W0q, const float* __restrict__ W0k, const float* __restrict__ W0v,
    const float* __restrict__ W1q, const float* __restrict__ W1k, const float* __restrict__ W1v) {
    int z = blockIdx.y;
    int i = blockIdx.x * blockDim.x + threadIdx.x;
    if (z < 12) {
        int c = z / 3, mm = z % 3;
        const float* W = (mm == 0 ? W0q : (mm == 1 ? W0k : W0v)) + (size_t)c * D_IN * D_HID;
        if (i < D_IN * D_HID) {
            int k = i / D_HID, n = i % D_HID;
            split_bf16(W[i], g_W0h[z][n * D_IN + k], g_W0l[z][n * D_IN + k]);
        }
    } else {
        int zz = z - 12;
        int c = zz / 3, mm = zz % 3;
        const float* W = (mm == 0 ? W1q : (mm == 1 ? W1k : W1v)) + (size_t)c * D_HID * D_OUT;
        if (i < D_HID * D_OUT) {
            int k = i / D_OUT, n = i % D_OUT;
            split_bf16(W[i], g_W1h[zz][n * D_HID + k], g_W1l[zz][n * D_HID + k]);
        }
    }
}

// ---------------- split-bf16 tensor-core GEMM: cp.async double-buffer + ldmatrix ------
__device__ __forceinline__ void mma_bf16(float* c, const uint32_t* a, const uint32_t* b) {
    asm volatile(
        "mma.sync.aligned.m16n8k16.row.col.f32.bf16.bf16.f32 "
        "{%0,%1,%2,%3}, {%4,%5,%6,%7}, {%8,%9}, {%0,%1,%2,%3};"
        : "+f"(c[0]), "+f"(c[1]), "+f"(c[2]), "+f"(c[3])
        : "r"(a[0]), "r"(a[1]), "r"(a[2]), "r"(a[3]), "r"(b[0]), "r"(b[1]));
}

__device__ __forceinline__ void ldsm_x4(uint32_t* r, uint32_t addr) {
    asm volatile("ldmatrix.sync.aligned.m8n8.x4.shared.b16 {%0,%1,%2,%3}, [%4];"
                 : "=r"(r[0]), "=r"(r[1]), "=r"(r[2]), "=r"(r[3]) : "r"(addr));
}

__device__ __forceinline__ void cp_async16(uint32_t dst, const void* src, bool valid) {
    int sz = valid ? 16 : 0;
    asm volatile("cp.async.cg.shared.global [%0], [%1], 16, %2;"
                 :: "r"(dst), "l"(src), "r"(sz));
}
__device__ __forceinline__ void cp_commit() {
    asm volatile("cp.async.commit_group;");
}
__device__ __forceinline__ void cp_wait0() {
    asm volatile("cp.async.wait_group 0;" ::: "memory");
}

// BM=128, BK=32, 256 threads = 8 warps (2M x 4N). 2-stage cp.async pipeline.
// Q (mm==0): full 3-term split, fp32 output.  K/V: 2-term split, fp16 output.
template <int LAYER, int BN>
__global__ void __launch_bounds__(256) qkv_gemm_bf16(
    const float* __restrict__ bq, const float* __restrict__ bk, const float* __restrict__ bv,
    int M) {
    constexpr int KD = 128;
    constexpr int BM = 128;
    constexpr int BK = 32;
    constexpr int MT = 4;
    constexpr int NT = BN / 32;
    constexpr int NP = NT / 2;
    constexpr int WNT = BN / 4;
    constexpr int ST = BK + 8;
    constexpr int NIT = KD / BK;
    constexpr uint32_t A_BYTES = BM * ST * 2;
    constexpr uint32_t B_BYTES = BN * ST * 2;
    constexpr uint32_t OFF_AL = 2 * A_BYTES;
    constexpr uint32_t OFF_BH = 4 * A_BYTES;
    constexpr uint32_t OFF_BL = 4 * A_BYTES + 2 * B_BYTES;

    extern __shared__ char smem[];
    uint32_t sb = (uint32_t)__cvta_generic_to_shared(smem);

    int z = blockIdx.z;
    int c = z / 3, mm = z % 3;
    const bool use_lo_a = (mm == 0);
    const __nv_bfloat16 *Ah_g, *Al_g, *Bh_g, *Bl_g;
    if (LAYER == 0) { Ah_g = g_Xh; Al_g = g_Xl; Bh_g = g_W0h[z]; Bl_g = g_W0l[z]; }
    else            { Ah_g = g_Hh; Al_g = g_Hl; Bh_g = g_W1h[z]; Bl_g = g_W1l[z]; }
    const float* bias = (mm == 0 ? bq : (mm == 1 ? bk : bv)) + (size_t)c * BN;
    float* Of = nullptr;
    __half* Oh = nullptr;
    if (LAYER == 0) {
        if (mm == 0) Of = g_Q0[c];
        else Oh = (mm == 1 ? g_K0[c] : g_V0[c]);
    } else {
        if (mm == 0) Of = g_Q1[c];
        else Oh = (mm == 1 ? g_K1[c] : g_V1[c]);
    }

    int tid = threadIdx.x;
    int warp = tid >> 5;
    int lane = tid & 31;
    int gid = lane >> 2;
    int tig = lane & 3;
    int wm = warp >> 2;
    int wn = warp & 3;
    int row0 = blockIdx.x * BM;
    int m0w = wm * 64;
    int n0w = wn * WNT;

    int mat = lane >> 3;
    int mrow = lane & 7;

    uint32_t aAddrH[MT], aAddrL[MT];
#pragma unroll
    for (int mt = 0; mt < MT; mt++) {
        int row = m0w + mt * 16 + ((mat & 1) << 3) + mrow;
        int col = (mat >> 1) << 3;
        uint32_t o = (row * ST + col) * 2;
        aAddrH[mt] = sb + o;
        aAddrL[mt] = sb + OFF_AL + o;
    }
    uint32_t bAddrH[NP], bAddrL[NP];
#pragma unroll
    for (int p = 0; p < NP; p++) {
        int row = n0w + p * 16 + ((mat >> 1) << 3) + mrow;
        int col = (mat & 1) << 3;
        uint32_t o = (row * ST + col) * 2;
        bAddrH[p] = sb + OFF_BH + o;
        bAddrL[p] = sb + OFF_BL + o;
    }

    float acc[MT][NT][4];
#pragma unroll
    for (int i = 0; i < MT; i++)
#pragma unroll
        for (int j = 0; j < NT; j++)
#pragma unroll
            for (int t = 0; t < 4; t++) acc[i][j][t] = 0.f;

    auto issue = [&](int it) {
        int st = it & 1;
        int k0 = it * BK;
        uint32_t aB = sb + st * A_BYTES;
        uint32_t aBl = sb + OFF_AL + st * A_BYTES;
#pragma unroll
        for (int f = tid; f < BM * BK / 8; f += 256) {
            int r = f >> 2, kc = (f & 3) * 8;
            int gr = row0 + r;
            bool v = gr < M;
            int gs = v ? gr : 0;
            uint32_t o = (r * ST + kc) * 2;
            cp_async16(aB + o, Ah_g + (size_t)gs * KD + k0 + kc, v);
            if (use_lo_a)
                cp_async16(aBl + o, Al_g + (size_t)gs * KD + k0 + kc, v);
        }
        uint32_t bB = sb + OFF_BH + st * B_BYTES;
        uint32_t bBl = sb + OFF_BL + st * B_BYTES;
#pragma unroll
        for (int f = tid; f < BN * BK / 8; f += 256) {
            int r = f >> 2, kc = (f & 3) * 8;
            uint32_t o = (r * ST + kc) * 2;
            cp_async16(bB + o, Bh_g + (size_t)r * KD + k0 + kc, true);
            cp_async16(bBl + o, Bl_g + (size_t)r * KD + k0 + kc, true);
        }
        cp_commit();
    };

    issue(0);

#pragma unroll
    for (int it = 0; it < NIT; it++) {
        cp_wait0();
        __syncthreads();
        if (it + 1 < NIT) issue(it + 1);
        uint32_t aoff = (uint32_t)(it & 1) * A_BYTES;
        uint32_t boff = (uint32_t)(it & 1) * B_BYTES;
#pragma unroll
        for (int s = 0; s < 2; s++) {
            uint32_t soff = s * 16 * 2;
            uint32_t bhr[NP][4], blr[NP][4];
#pragma unroll
            for (int p = 0; p < NP; p++) {
                ldsm_x4(bhr[p], bAddrH[p] + boff + soff);
                ldsm_x4(blr[p], bAddrL[p] + boff + soff);
            }
#pragma unroll
            for (int mt = 0; mt < MT; mt++) {
                uint32_t ah[4], al[4];
                ldsm_x4(ah, aAddrH[mt] + aoff + soff);
                if (use_lo_a) ldsm_x4(al, aAddrL[mt] + aoff + soff);
#pragma unroll
                for (int nt = 0; nt < NT; nt++) {
                    const uint32_t* bh2 = &bhr[nt >> 1][(nt & 1) * 2];
                    const uint32_t* bl2 = &blr[nt >> 1][(nt & 1) * 2];
                    mma_bf16(acc[mt][nt], ah, bh2);
                    mma_bf16(acc[mt][nt], ah, bl2);
                    if (use_lo_a) mma_bf16(acc[mt][nt], al, bh2);
                }
            }
        }
    }

#pragma unroll
    for (int mt = 0; mt < MT; mt++) {
        int r0 = row0 + m0w + mt * 16 + gid;
        int r1 = r0 + 8;
#pragma unroll
        for (int nt = 0; nt < NT; nt++) {
            int col = n0w + nt * 8 + 2 * tig;
            float bx = bias[col], by = bias[col + 1];
            if (mm == 0) {
                if (r0 < M)
                    *(float2*)(Of + (size_t)r0 * BN + col) =
                        make_float2(acc[mt][nt][0] + bx, acc[mt][nt][1] + by);
                if (r1 < M)
                    *(float2*)(Of + (size_t)r1 * BN + col) =
                        make_float2(acc[mt][nt][2] + bx, acc[mt][nt][3] + by);
            } else {
                if (r0 < M)
                    *(__half2*)(Oh + (size_t)r0 * BN + col) =
                        __floats2half2_rn(acc[mt][nt][0] + bx, acc[mt][nt][1] + by);
                if (r1 < M)
                    *(__half2*)(Oh + (size_t)r1 * BN + col) =
                        __floats2half2_rn(acc[mt][nt][2] + bx, acc[mt][nt][3] + by);
            }
        }
    }
}

// ---------------- layer-0 fused attention: BOTH hops (4 combos) in one kernel --------
// hop0: combos {0,2} beta 1.0; hop1: combos {1,3} beta 0.25.
// g_H = elu(sum), plus split-bf16 copies for the layer-1 GEMM.
__global__ void attn0_fused_kernel(int n) {
    int gw = (blockIdx.x * blockDim.x + threadIdx.x) >> 5;
    if (gw >= n) return;
    int lane = threadIdx.x & 31;
    const float scale = 0.17677669529663687f;  // 1/sqrt(32)
    size_t off = (size_t)gw * 128 + lane * 4;

    float4 y = make_float4(0.f, 0.f, 0.f, 0.f);

#pragma unroll
    for (int hop = 0; hop < 2; hop++) {
        int cA = hop;       // 0 or 1
        int cB = hop + 2;   // 2 or 3
        float beta = hop ? 0.25f : 1.0f;
        const float* __restrict__ QA = g_Q0[cA];
        const __half* __restrict__ KA = g_K0[cA];
        const __half* __restrict__ VA = g_V0[cA];
        const float* __restrict__ QB = g_Q0[cB];
        const __half* __restrict__ KB = g_K0[cB];
        const __half* __restrict__ VB = g_V0[cB];
        const int* __restrict__ cols = g_cols[hop];

        float4 qa = *(const float4*)(QA + off);
        float4 qb = *(const float4*)(QB + off);
        float4 aA = make_float4(0.f, 0.f, 0.f, 0.f);
        float4 aB = make_float4(0.f, 0.f, 0.f, 0.f);
        float mA = -INFINITY, lA = 0.f, mB = -INFINITY, lB = 0.f;

        int s0 = g_rowptr[hop][gw], s1 = g_rowptr[hop][gw + 1];
        uint2 kraN, krbN, vraN, vrbN;
        if (s0 < s1) {
            size_t co = (size_t)cols[s0] * 128 + lane * 4;
            kraN = *(const uint2*)(KA + co);
            krbN = *(const uint2*)(KB + co);
            vraN = *(const uint2*)(VA + co);
            vrbN = *(const uint2*)(VB + co);
        }
        for (int p = s0; p < s1; p++) {
            uint2 kra = kraN, krb = krbN, vra = vraN, vrb = vrbN;
            if (p + 1 < s1) {
                size_t co = (size_t)cols[p + 1] * 128 + lane * 4;
                kraN = *(const uint2*)(KA + co);
                krbN = *(const uint2*)(KB + co);
                vraN = *(const uint2*)(VA + co);
                vrbN = *(const uint2*)(VB + co);
            }
            float2 ka01 = __half22float2(*(__half2*)&kra.x);
            float2 ka23 = __half22float2(*(__half2*)&kra.y);
            float2 kb01 = __half22float2(*(__half2*)&krb.x);
            float2 kb23 = __half22float2(*(__half2*)&krb.y);
            float dA = qa.x * ka01.x + qa.y * ka01.y + qa.z * ka23.x + qa.w * ka23.y;
            float dB = qb.x * kb01.x + qb.y * kb01.y + qb.z * kb23.x + qb.w * kb23.y;
            dA += __shfl_xor_sync(0xffffffffu, dA, 1);
            dA += __shfl_xor_sync(0xffffffffu, dA, 2);
            dA += __shfl_xor_sync(0xffffffffu, dA, 4);
            dB += __shfl_xor_sync(0xffffffffu, dB, 1);
            dB += __shfl_xor_sync(0xffffffffu, dB, 2);
            dB += __shfl_xor_sync(0xffffffffu, dB, 4);
            float2 va01 = __half22float2(*(__half2*)&vra.x);
            float2 va23 = __half22float2(*(__half2*)&vra.y);
            float2 vb01 = __half22float2(*(__half2*)&vrb.x);
            float2 vb23 = __half22float2(*(__half2*)&vrb.y);
            {
                float s = dA * scale;
                float nm = fmaxf(mA, s);
                float sc = __expf(mA - nm);
                float pe = __expf(s - nm);
                lA = lA * sc + pe;
                aA.x = aA.x * sc + pe * va01.x; aA.y = aA.y * sc + pe * va01.y;
                aA.z = aA.z * sc + pe * va23.x; aA.w = aA.w * sc + pe * va23.y;
                mA = nm;
            }
            {
                float s = dB * scale;
                float nm = fmaxf(mB, s);
                float sc = __expf(mB - nm);
                float pe = __expf(s - nm);
                lB = lB * sc + pe;
                aB.x = aB.x * sc + pe * vb01.x; aB.y = aB.y * sc + pe * vb01.y;
                aB.z = aB.z * sc + pe * vb23.x; aB.w = aB.w * sc + pe * vb23.y;
                mB = nm;
            }
        }
        float wA = beta / (lA + 1e-16f);
        float wB = beta / (lB + 1e-16f);
        y.x += aA.x * wA + aB.x * wB;
        y.y += aA.y * wA + aB.y * wB;
        y.z += aA.z * wA + aB.z * wB;
        y.w += aA.w * wA + aB.w * wB;
    }

    // elu + store fp32 + split-bf16
    y.x = y.x > 0.f ? y.x : expm1f(y.x);
    y.y = y.y > 0.f ? y.y : expm1f(y.y);
    y.z = y.z > 0.f ? y.z : expm1f(y.z);
    y.w = y.w > 0.f ? y.w : expm1f(y.w);
    *(float4*)(g_H + off) = y;
    float vals[4] = {y.x, y.y, y.z, y.w};
#pragma unroll
    for (int t = 0; t < 4; t++) split_bf16(vals[t], g_Hh[off + t], g_Hl[off + t]);
}

// ---------------- layer-1 fused attention: both hops + log_softmax -------------------
__global__ void attn1_fused_kernel(float* __restrict__ out, int n) {
    int gw = (blockIdx.x * blockDim.x + threadIdx.x) >> 5;
    if (gw >= n) return;
    int lane = threadIdx.x & 31;
    const float scale = 0.25f;  // 1/sqrt(16)
    size_t off = (size_t)gw * 64 + lane * 2;

    float2 res = make_float2(0.f, 0.f);
#pragma unroll
    for (int combo = 0; combo < 2; combo++) {
        const float* __restrict__ Q = g_Q1[combo];
        const __half* __restrict__ Kp = g_K1[combo];
        const __half* __restrict__ Vp = g_V1[combo];
        const int* __restrict__ cols = g_cols[combo];
        float beta = (combo == 0) ? 1.0f : 0.25f;

        float2 q = *(const float2*)(Q + off);
        float2 acc = make_float2(0.f, 0.f);
        float m = -INFINITY, l = 0.f;

        int s0 = g_rowptr[combo][gw], s1 = g_rowptr[combo][gw + 1];
        uint32_t krN, vrN;
        if (s0 < s1) {
            size_t co = (size_t)cols[s0] * 64 + lane * 2;
            krN = *(const uint32_t*)(Kp + co);
            vrN = *(const uint32_t*)(Vp + co);
        }
        for (int p = s0; p < s1; p++) {
            uint32_t kr = krN, vr = vrN;
            if (p + 1 < s1) {
                size_t co = (size_t)cols[p + 1] * 64 + lane * 2;
                krN = *(const uint32_t*)(Kp + co);
                vrN = *(const uint32_t*)(Vp + co);
            }
            float2 k = __half22float2(*(__half2*)&kr);
            float d = q.x * k.x + q.y * k.y;
            d += __shfl_xor_sync(0xffffffffu, d, 1);
            d += __shfl_xor_sync(0xffffffffu, d, 2);
            d += __shfl_xor_sync(0xffffffffu, d, 4);
            float2 v = __half22float2(*(__half2*)&vr);
            float s = d * scale;
            float nm = fmaxf(m, s);
            float sc = __expf(m - nm);
            float pe = __expf(s - nm);
            l = l * sc + pe;
            acc.x = acc.x * sc + pe * v.x;
            acc.y = acc.y * sc + pe * v.y;
            m = nm;
        }
        float w = beta / (l + 1e-16f);
        res.x += acc.x * w;
        res.y += acc.y * w;
    }

    float mx = fmaxf(res.x, res.y);
#pragma unroll
    for (int o = 16; o; o >>= 1) mx = fmaxf(mx, __shfl_xor_sync(0xffffffffu, mx, o));
    float s = expf(res.x - mx) + expf(res.y - mx);
#pragma unroll
    for (int o = 16; o; o >>= 1) s += __shfl_xor_sync(0xffffffffu, s, o);
    float lg = mx + logf(s);
    res.x -= lg; res.y -= lg;
    *(float2*)(out + off) = res;
}

// ---------------- launch ----------------
extern "C" void kernel_launch(void* const* d_in, const int* in_sizes, int n_in,
                              void* d_out, int out_size) {
    const float* x   = (const float*)d_in[0];
    const int* edge0 = (const int*)d_in[1];
    const int* edge1 = (const int*)d_in[2];
    const float* W0q = (const float*)d_in[3];
    const float* W0k = (const float*)d_in[4];
    const float* W0v = (const float*)d_in[5];
    const float* b0q = (const float*)d_in[6];
    const float* b0k = (const float*)d_in[7];
    const float* b0v = (const float*)d_in[8];
    const float* W1q = (const float*)d_in[9];
    const float* W1k = (const float*)d_in[10];
    const float* W1v = (const float*)d_in[11];
    const float* b1q = (const float*)d_in[12];
    const float* b1k = (const float*)d_in[13];
    const float* b1v = (const float*)d_in[14];
    float* out = (float*)d_out;

    int M = in_sizes[0] / D_IN;   // 50000
    int E = in_sizes[1] / 2;      // 400000
    int nb = (M + 255) / 256;
    int eb = (E + 255) / 256;

    // one-time host-side setup (first call is the pre-capture correctness run)
    static cudaStream_t s2 = nullptr;
    static cudaEvent_t evFork = nullptr, evJoin = nullptr;
    static bool init_done = false;
    if (!init_done) {
        cudaFuncSetAttribute(qkv_gemm_bf16<0, 128>,
                             cudaFuncAttributeMaxDynamicSharedMemorySize, 81920);
        cudaFuncSetAttribute(qkv_gemm_bf16<1, 64>,
                             cudaFuncAttributeMaxDynamicSharedMemorySize, 61440);
        cudaStreamCreateWithFlags(&s2, cudaStreamNonBlocking);
        cudaEventCreateWithFlags(&evFork, cudaEventDisableTiming);
        cudaEventCreateWithFlags(&evJoin, cudaEventDisableTiming);
        init_done = true;
    }

    // fork: CSR build runs on s2 concurrently with split+GEMM0 on the default stream
    cudaEventRecord(evFork, 0);
    cudaStreamWaitEvent(s2, evFork, 0);

    split_x_kernel<<<(M * D_IN + 255) / 256, 256>>>(x, M * D_IN);       // 1
    split_w_kernel<<<dim3(64, 18), 256>>>(W0q, W0k, W0v,                // 2
                                          W1q, W1k, W1v);
    zero2_kernel<<<dim3(nb, 2), 256, 0, s2>>>(M);                       // 3 (s2)

    dim3 g0((M + 127) / 128, 1, 12);
    qkv_gemm_bf16<0, 128><<<g0, 256, 81920>>>(b0q, b0k, b0v, M);        // 4 <- profiled

    count2_kernel<<<dim3(eb, 2), 256, 0, s2>>>(edge0, edge1, E);        // (s2)
    scanA_kernel<<<dim3(nb, 2), 256, 0, s2>>>(M);                       // (s2)
    scanB_kernel<<<1, 256, 0, s2>>>(nb);                                // (s2)
    scanC_kernel<<<dim3(nb, 2), 256, 0, s2>>>(M, E);                    // (s2)
    scatter2_kernel<<<dim3(eb, 2), 256, 0, s2>>>(edge0, edge1, E);      // (s2)
    cudaEventRecord(evJoin, s2);
    cudaStreamWaitEvent(0, evJoin, 0);

    int ab = (M * 32 + 255) / 256;
    attn0_fused_kernel<<<ab, 256>>>(M);

    dim3 g1((M + 127) / 128, 1, 6);
    qkv_gemm_bf16<1, 64><<<g1, 256, 61440>>>(b1q, b1k, b1v, M);

    attn1_fused_kernel<<<ab, 256>>>(out, M);
}

// round 15
// speedup vs baseline: 1.0181x; 1.0181x over previous
#include <cuda_runtime.h>
#include <cuda_fp16.h>
#include <math.h>
#include <stdint.h>

#define NN 50000
#define EE 400000
#define D_IN 128
#define D_HID 128
#define D_OUT 64

// ---------------- scratch ----------------
__device__ float g_Q0[4][NN * D_HID];
__device__ __half g_K0[4][NN * D_HID];
__device__ __half g_V0[4][NN * D_HID];
__device__ float g_H[NN * D_HID];
__device__ float g_Q1[2][NN * D_OUT];
__device__ __half g_K1[2][NN * D_OUT];
__device__ __half g_V1[2][NN * D_OUT];
__device__ int g_deg[2][NN];
__device__ int g_scan[2][NN];
__device__ int g_bsum[2][256];
__device__ int g_boff[2][256];
__device__ int g_cursor[2][NN];
__device__ int g_rowptr[2][NN + 1];
__device__ int g_cols[2][EE];

// split-fp16 operands (hi + lo), weights stored transposed [n][k]
__device__ __half g_Xh[NN * D_IN], g_Xl[NN * D_IN];
__device__ __half g_Hh[NN * D_HID], g_Hl[NN * D_HID];
__device__ __half g_W0h[12][D_HID * D_IN], g_W0l[12][D_HID * D_IN];
__device__ __half g_W1h[6][D_OUT * D_HID], g_W1l[6][D_OUT * D_HID];

__device__ __forceinline__ void split_fp16(float v, __half& h, __half& l) {
    h = __float2half_rn(v);
    l = __float2half_rn(v - __half2float(h));
}

// ---------------- CSR build ----------------
__global__ void zero2_kernel(int n) {
    int i = blockIdx.x * blockDim.x + threadIdx.x;
    if (i < n) g_deg[blockIdx.y][i] = 0;
}

__global__ void count2_kernel(const int* __restrict__ e0, const int* __restrict__ e1, int e) {
    int i = blockIdx.x * blockDim.x + threadIdx.x;
    int hop = blockIdx.y;
    const int* rows = hop ? e1 : e0;
    if (i < e) atomicAdd(&g_deg[hop][rows[i]], 1);
}

__global__ void scanA_kernel(int n) {
    int hop = blockIdx.y;
    int chunk = blockIdx.x;
    int tid = threadIdx.x;
    int i = chunk * 256 + tid;
    int v = (i < n) ? g_deg[hop][i] : 0;
    __shared__ int sm[256];
    sm[tid] = v;
    __syncthreads();
#pragma unroll
    for (int off = 1; off < 256; off <<= 1) {
        int t = (tid >= off) ? sm[tid - off] : 0;
        __syncthreads();
        sm[tid] += t;
        __syncthreads();
    }
    if (i < n) g_scan[hop][i] = sm[tid] - v;
    if (tid == 255) g_bsum[hop][chunk] = sm[255];
}

__global__ void scanB_kernel(int nblk) {
    __shared__ int sm[256];
    int tid = threadIdx.x;
    for (int hop = 0; hop < 2; hop++) {
        int v = (tid < nblk) ? g_bsum[hop][tid] : 0;
        sm[tid] = v;
        __syncthreads();
#pragma unroll
        for (int off = 1; off < 256; off <<= 1) {
            int t = (tid >= off) ? sm[tid - off] : 0;
            __syncthreads();
            sm[tid] += t;
            __syncthreads();
        }
        if (tid < nblk) g_boff[hop][tid] = sm[tid] - v;
        __syncthreads();
    }
}

__global__ void scanC_kernel(int n, int e) {
    int i = blockIdx.x * blockDim.x + threadIdx.x;
    int hop = blockIdx.y;
    if (i < n) {
        int rp = g_scan[hop][i] + g_boff[hop][i >> 8];
        g_rowptr[hop][i] = rp;
        g_cursor[hop][i] = rp;
        if (i == 0) g_rowptr[hop][n] = e;
    }
}

__global__ void scatter2_kernel(const int* __restrict__ e0, const int* __restrict__ e1, int e) {
    int i = blockIdx.x * blockDim.x + threadIdx.x;
    int hop = blockIdx.y;
    const int* rows = hop ? e1 : e0;
    if (i < e) {
        int r = rows[i];
        int c = rows[i + e];
        int p = atomicAdd(&g_cursor[hop][r], 1);
        g_cols[hop][p] = c;
    }
}

// ---------------- split precompute ----------------
__global__ void split_x_kernel(const float* __restrict__ x, int n) {
    int i = blockIdx.x * blockDim.x + threadIdx.x;
    if (i < n) split_fp16(x[i], g_Xh[i], g_Xl[i]);
}

__global__ void split_w_kernel(
    const float* __restrict__ W0q, const float* __restrict__ W0k, const float* __restrict__ W0v,
    const float* __restrict__ W1q, const float* __restrict__ W1k, const float* __restrict__ W1v) {
    int z = blockIdx.y;
    int i = blockIdx.x * blockDim.x + threadIdx.x;
    if (z < 12) {
        int c = z / 3, mm = z % 3;
        const float* W = (mm == 0 ? W0q : (mm == 1 ? W0k : W0v)) + (size_t)c * D_IN * D_HID;
        if (i < D_IN * D_HID) {
            int k = i / D_HID, n = i % D_HID;
            split_fp16(W[i], g_W0h[z][n * D_IN + k], g_W0l[z][n * D_IN + k]);
        }
    } else {
        int zz = z - 12;
        int c = zz / 3, mm = zz % 3;
        const float* W = (mm == 0 ? W1q : (mm == 1 ? W1k : W1v)) + (size_t)c * D_HID * D_OUT;
        if (i < D_HID * D_OUT) {
            int k = i / D_OUT, n = i % D_OUT;
            split_fp16(W[i], g_W1h[zz][n * D_HID + k], g_W1l[zz][n * D_HID + k]);
        }
    }
}

// ---------------- split-fp16 tensor-core GEMM: cp.async double-buffer + ldmatrix ------
// Q (mm==0): 3-term fp16 split (AhBh + AhBl + AlBh), fp32 output -> ~2^-21 accuracy.
// K/V (mm!=0): SINGLE term AhBh (fp16 ~2^-11, better than old 2-term bf16), fp16 out.
__device__ __forceinline__ void mma_f16(float* c, const uint32_t* a, const uint32_t* b) {
    asm volatile(
        "mma.sync.aligned.m16n8k16.row.col.f32.f16.f16.f32 "
        "{%0,%1,%2,%3}, {%4,%5,%6,%7}, {%8,%9}, {%0,%1,%2,%3};"
        : "+f"(c[0]), "+f"(c[1]), "+f"(c[2]), "+f"(c[3])
        : "r"(a[0]), "r"(a[1]), "r"(a[2]), "r"(a[3]), "r"(b[0]), "r"(b[1]));
}

__device__ __forceinline__ void ldsm_x4(uint32_t* r, uint32_t addr) {
    asm volatile("ldmatrix.sync.aligned.m8n8.x4.shared.b16 {%0,%1,%2,%3}, [%4];"
                 : "=r"(r[0]), "=r"(r[1]), "=r"(r[2]), "=r"(r[3]) : "r"(addr));
}

__device__ __forceinline__ void cp_async16(uint32_t dst, const void* src, bool valid) {
    int sz = valid ? 16 : 0;
    asm volatile("cp.async.cg.shared.global [%0], [%1], 16, %2;"
                 :: "r"(dst), "l"(src), "r"(sz));
}
__device__ __forceinline__ void cp_commit() {
    asm volatile("cp.async.commit_group;");
}
__device__ __forceinline__ void cp_wait0() {
    asm volatile("cp.async.wait_group 0;" ::: "memory");
}

// BM=128, BK=32, 256 threads = 8 warps (2M x 4N). 2-stage cp.async pipeline.
template <int LAYER, int BN>
__global__ void __launch_bounds__(256) qkv_gemm_f16(
    const float* __restrict__ bq, const float* __restrict__ bk, const float* __restrict__ bv,
    int M) {
    constexpr int KD = 128;
    constexpr int BM = 128;
    constexpr int BK = 32;
    constexpr int MT = 4;
    constexpr int NT = BN / 32;
    constexpr int NP = NT / 2;
    constexpr int WNT = BN / 4;
    constexpr int ST = BK + 8;
    constexpr int NIT = KD / BK;
    constexpr uint32_t A_BYTES = BM * ST * 2;
    constexpr uint32_t B_BYTES = BN * ST * 2;
    constexpr uint32_t OFF_AL = 2 * A_BYTES;
    constexpr uint32_t OFF_BH = 4 * A_BYTES;
    constexpr uint32_t OFF_BL = 4 * A_BYTES + 2 * B_BYTES;

    extern __shared__ char smem[];
    uint32_t sb = (uint32_t)__cvta_generic_to_shared(smem);

    int z = blockIdx.z;
    int c = z / 3, mm = z % 3;
    const bool full = (mm == 0);   // 3-term for Q; 1-term for K/V
    const __half *Ah_g, *Al_g, *Bh_g, *Bl_g;
    if (LAYER == 0) { Ah_g = g_Xh; Al_g = g_Xl; Bh_g = g_W0h[z]; Bl_g = g_W0l[z]; }
    else            { Ah_g = g_Hh; Al_g = g_Hl; Bh_g = g_W1h[z]; Bl_g = g_W1l[z]; }
    const float* bias = (mm == 0 ? bq : (mm == 1 ? bk : bv)) + (size_t)c * BN;
    float* Of = nullptr;
    __half* Oh = nullptr;
    if (LAYER == 0) {
        if (mm == 0) Of = g_Q0[c];
        else Oh = (mm == 1 ? g_K0[c] : g_V0[c]);
    } else {
        if (mm == 0) Of = g_Q1[c];
        else Oh = (mm == 1 ? g_K1[c] : g_V1[c]);
    }

    int tid = threadIdx.x;
    int warp = tid >> 5;
    int lane = tid & 31;
    int gid = lane >> 2;
    int tig = lane & 3;
    int wm = warp >> 2;
    int wn = warp & 3;
    int row0 = blockIdx.x * BM;
    int m0w = wm * 64;
    int n0w = wn * WNT;

    int mat = lane >> 3;
    int mrow = lane & 7;

    uint32_t aAddrH[MT], aAddrL[MT];
#pragma unroll
    for (int mt = 0; mt < MT; mt++) {
        int row = m0w + mt * 16 + ((mat & 1) << 3) + mrow;
        int col = (mat >> 1) << 3;
        uint32_t o = (row * ST + col) * 2;
        aAddrH[mt] = sb + o;
        aAddrL[mt] = sb + OFF_AL + o;
    }
    uint32_t bAddrH[NP], bAddrL[NP];
#pragma unroll
    for (int p = 0; p < NP; p++) {
        int row = n0w + p * 16 + ((mat >> 1) << 3) + mrow;
        int col = (mat & 1) << 3;
        uint32_t o = (row * ST + col) * 2;
        bAddrH[p] = sb + OFF_BH + o;
        bAddrL[p] = sb + OFF_BL + o;
    }

    float acc[MT][NT][4];
#pragma unroll
    for (int i = 0; i < MT; i++)
#pragma unroll
        for (int j = 0; j < NT; j++)
#pragma unroll
            for (int t = 0; t < 4; t++) acc[i][j][t] = 0.f;

    auto issue = [&](int it) {
        int st = it & 1;
        int k0 = it * BK;
        uint32_t aB = sb + st * A_BYTES;
        uint32_t aBl = sb + OFF_AL + st * A_BYTES;
#pragma unroll
        for (int f = tid; f < BM * BK / 8; f += 256) {
            int r = f >> 2, kc = (f & 3) * 8;
            int gr = row0 + r;
            bool v = gr < M;
            int gs = v ? gr : 0;
            uint32_t o = (r * ST + kc) * 2;
            cp_async16(aB + o, Ah_g + (size_t)gs * KD + k0 + kc, v);
            if (full)
                cp_async16(aBl + o, Al_g + (size_t)gs * KD + k0 + kc, v);
        }
        uint32_t bB = sb + OFF_BH + st * B_BYTES;
        uint32_t bBl = sb + OFF_BL + st * B_BYTES;
#pragma unroll
        for (int f = tid; f < BN * BK / 8; f += 256) {
            int r = f >> 2, kc = (f & 3) * 8;
            uint32_t o = (r * ST + kc) * 2;
            cp_async16(bB + o, Bh_g + (size_t)r * KD + k0 + kc, true);
            if (full)
                cp_async16(bBl + o, Bl_g + (size_t)r * KD + k0 + kc, true);
        }
        cp_commit();
    };

    issue(0);

#pragma unroll
    for (int it = 0; it < NIT; it++) {
        cp_wait0();
        __syncthreads();
        if (it + 1 < NIT) issue(it + 1);
        uint32_t aoff = (uint32_t)(it & 1) * A_BYTES;
        uint32_t boff = (uint32_t)(it & 1) * B_BYTES;
#pragma unroll
        for (int s = 0; s < 2; s++) {
            uint32_t soff = s * 16 * 2;
            uint32_t bhr[NP][4], blr[NP][4];
#pragma unroll
            for (int p = 0; p < NP; p++) {
                ldsm_x4(bhr[p], bAddrH[p] + boff + soff);
                if (full) ldsm_x4(blr[p], bAddrL[p] + boff + soff);
            }
#pragma unroll
            for (int mt = 0; mt < MT; mt++) {
                uint32_t ah[4], al[4];
                ldsm_x4(ah, aAddrH[mt] + aoff + soff);
                if (full) ldsm_x4(al, aAddrL[mt] + aoff + soff);
#pragma unroll
                for (int nt = 0; nt < NT; nt++) {
                    const uint32_t* bh2 = &bhr[nt >> 1][(nt & 1) * 2];
                    mma_f16(acc[mt][nt], ah, bh2);
                    if (full) {
                        const uint32_t* bl2 = &blr[nt >> 1][(nt & 1) * 2];
                        mma_f16(acc[mt][nt], ah, bl2);
                        mma_f16(acc[mt][nt], al, bh2);
                    }
                }
            }
        }
    }

#pragma unroll
    for (int mt = 0; mt < MT; mt++) {
        int r0 = row0 + m0w + mt * 16 + gid;
        int r1 = r0 + 8;
#pragma unroll
        for (int nt = 0; nt < NT; nt++) {
            int col = n0w + nt * 8 + 2 * tig;
            float bx = bias[col], by = bias[col + 1];
            if (mm == 0) {
                if (r0 < M)
                    *(float2*)(Of + (size_t)r0 * BN + col) =
                        make_float2(acc[mt][nt][0] + bx, acc[mt][nt][1] + by);
                if (r1 < M)
                    *(float2*)(Of + (size_t)r1 * BN + col) =
                        make_float2(acc[mt][nt][2] + bx, acc[mt][nt][3] + by);
            } else {
                if (r0 < M)
                    *(__half2*)(Oh + (size_t)r0 * BN + col) =
                        __floats2half2_rn(acc[mt][nt][0] + bx, acc[mt][nt][1] + by);
                if (r1 < M)
                    *(__half2*)(Oh + (size_t)r1 * BN + col) =
                        __floats2half2_rn(acc[mt][nt][2] + bx, acc[mt][nt][3] + by);
            }
        }
    }
}

// ---------------- layer-0 fused attention: BOTH hops (4 combos) in one kernel --------
__global__ void attn0_fused_kernel(int n) {
    int gw = (blockIdx.x * blockDim.x + threadIdx.x) >> 5;
    if (gw >= n) return;
    int lane = threadIdx.x & 31;
    const float scale = 0.17677669529663687f;  // 1/sqrt(32)
    size_t off = (size_t)gw * 128 + lane * 4;

    float4 y = make_float4(0.f, 0.f, 0.f, 0.f);

#pragma unroll
    for (int hop = 0; hop < 2; hop++) {
        int cA = hop;
        int cB = hop + 2;
        float beta = hop ? 0.25f : 1.0f;
        const float* __restrict__ QA = g_Q0[cA];
        const __half* __restrict__ KA = g_K0[cA];
        const __half* __restrict__ VA = g_V0[cA];
        const float* __restrict__ QB = g_Q0[cB];
        const __half* __restrict__ KB = g_K0[cB];
        const __half* __restrict__ VB = g_V0[cB];
        const int* __restrict__ cols = g_cols[hop];

        float4 qa = *(const float4*)(QA + off);
        float4 qb = *(const float4*)(QB + off);
        float4 aA = make_float4(0.f, 0.f, 0.f, 0.f);
        float4 aB = make_float4(0.f, 0.f, 0.f, 0.f);
        float mA = -INFINITY, lA = 0.f, mB = -INFINITY, lB = 0.f;

        int s0 = g_rowptr[hop][gw], s1 = g_rowptr[hop][gw + 1];
        uint2 kraN, krbN, vraN, vrbN;
        if (s0 < s1) {
            size_t co = (size_t)cols[s0] * 128 + lane * 4;
            kraN = *(const uint2*)(KA + co);
            krbN = *(const uint2*)(KB + co);
            vraN = *(const uint2*)(VA + co);
            vrbN = *(const uint2*)(VB + co);
        }
        for (int p = s0; p < s1; p++) {
            uint2 kra = kraN, krb = krbN, vra = vraN, vrb = vrbN;
            if (p + 1 < s1) {
                size_t co = (size_t)cols[p + 1] * 128 + lane * 4;
                kraN = *(const uint2*)(KA + co);
                krbN = *(const uint2*)(KB + co);
                vraN = *(const uint2*)(VA + co);
                vrbN = *(const uint2*)(VB + co);
            }
            float2 ka01 = __half22float2(*(__half2*)&kra.x);
            float2 ka23 = __half22float2(*(__half2*)&kra.y);
            float2 kb01 = __half22float2(*(__half2*)&krb.x);
            float2 kb23 = __half22float2(*(__half2*)&krb.y);
            float dA = qa.x * ka01.x + qa.y * ka01.y + qa.z * ka23.x + qa.w * ka23.y;
            float dB = qb.x * kb01.x + qb.y * kb01.y + qb.z * kb23.x + qb.w * kb23.y;
            dA += __shfl_xor_sync(0xffffffffu, dA, 1);
            dA += __shfl_xor_sync(0xffffffffu, dA, 2);
            dA += __shfl_xor_sync(0xffffffffu, dA, 4);
            dB += __shfl_xor_sync(0xffffffffu, dB, 1);
            dB += __shfl_xor_sync(0xffffffffu, dB, 2);
            dB += __shfl_xor_sync(0xffffffffu, dB, 4);
            float2 va01 = __half22float2(*(__half2*)&vra.x);
            float2 va23 = __half22float2(*(__half2*)&vra.y);
            float2 vb01 = __half22float2(*(__half2*)&vrb.x);
            float2 vb23 = __half22float2(*(__half2*)&vrb.y);
            {
                float s = dA * scale;
                float nm = fmaxf(mA, s);
                float sc = __expf(mA - nm);
                float pe = __expf(s - nm);
                lA = lA * sc + pe;
                aA.x = aA.x * sc + pe * va01.x; aA.y = aA.y * sc + pe * va01.y;
                aA.z = aA.z * sc + pe * va23.x; aA.w = aA.w * sc + pe * va23.y;
                mA = nm;
            }
            {
                float s = dB * scale;
                float nm = fmaxf(mB, s);
                float sc = __expf(mB - nm);
                float pe = __expf(s - nm);
                lB = lB * sc + pe;
                aB.x = aB.x * sc + pe * vb01.x; aB.y = aB.y * sc + pe * vb01.y;
                aB.z = aB.z * sc + pe * vb23.x; aB.w = aB.w * sc + pe * vb23.y;
                mB = nm;
            }
        }
        float wA = beta / (lA + 1e-16f);
        float wB = beta / (lB + 1e-16f);
        y.x += aA.x * wA + aB.x * wB;
        y.y += aA.y * wA + aB.y * wB;
        y.z += aA.z * wA + aB.z * wB;
        y.w += aA.w * wA + aB.w * wB;
    }

    y.x = y.x > 0.f ? y.x : expm1f(y.x);
    y.y = y.y > 0.f ? y.y : expm1f(y.y);
    y.z = y.z > 0.f ? y.z : expm1f(y.z);
    y.w = y.w > 0.f ? y.w : expm1f(y.w);
    *(float4*)(g_H + off) = y;
    float vals[4] = {y.x, y.y, y.z, y.w};
#pragma unroll
    for (int t = 0; t < 4; t++) split_fp16(vals[t], g_Hh[off + t], g_Hl[off + t]);
}

// ---------------- layer-1 fused attention: both hops + log_softmax -------------------
__global__ void attn1_fused_kernel(float* __restrict__ out, int n) {
    int gw = (blockIdx.x * blockDim.x + threadIdx.x) >> 5;
    if (gw >= n) return;
    int lane = threadIdx.x & 31;
    const float scale = 0.25f;  // 1/sqrt(16)
    size_t off = (size_t)gw * 64 + lane * 2;

    float2 res = make_float2(0.f, 0.f);
#pragma unroll
    for (int combo = 0; combo < 2; combo++) {
        const float* __restrict__ Q = g_Q1[combo];
        const __half* __restrict__ Kp = g_K1[combo];
        const __half* __restrict__ Vp = g_V1[combo];
        const int* __restrict__ cols = g_cols[combo];
        float beta = (combo == 0) ? 1.0f : 0.25f;

        float2 q = *(const float2*)(Q + off);
        float2 acc = make_float2(0.f, 0.f);
        float m = -INFINITY, l = 0.f;

        int s0 = g_rowptr[combo][gw], s1 = g_rowptr[combo][gw + 1];
        uint32_t krN, vrN;
        if (s0 < s1) {
            size_t co = (size_t)cols[s0] * 64 + lane * 2;
            krN = *(const uint32_t*)(Kp + co);
            vrN = *(const uint32_t*)(Vp + co);
        }
        for (int p = s0; p < s1; p++) {
            uint32_t kr = krN, vr = vrN;
            if (p + 1 < s1) {
                size_t co = (size_t)cols[p + 1] * 64 + lane * 2;
                krN = *(const uint32_t*)(Kp + co);
                vrN = *(const uint32_t*)(Vp + co);
            }
            float2 k = __half22float2(*(__half2*)&kr);
            float d = q.x * k.x + q.y * k.y;
            d += __shfl_xor_sync(0xffffffffu, d, 1);
            d += __shfl_xor_sync(0xffffffffu, d, 2);
            d += __shfl_xor_sync(0xffffffffu, d, 4);
            float2 v = __half22float2(*(__half2*)&vr);
            float s = d * scale;
            float nm = fmaxf(m, s);
            float sc = __expf(m - nm);
            float pe = __expf(s - nm);
            l = l * sc + pe;
            acc.x = acc.x * sc + pe * v.x;
            acc.y = acc.y * sc + pe * v.y;
            m = nm;
        }
        float w = beta / (l + 1e-16f);
        res.x += acc.x * w;
        res.y += acc.y * w;
    }

    float mx = fmaxf(res.x, res.y);
#pragma unroll
    for (int o = 16; o; o >>= 1) mx = fmaxf(mx, __shfl_xor_sync(0xffffffffu, mx, o));
    float s = expf(res.x - mx) + expf(res.y - mx);
#pragma unroll
    for (int o = 16; o; o >>= 1) s += __shfl_xor_sync(0xffffffffu, s, o);
    float lg = mx + logf(s);
    res.x -= lg; res.y -= lg;
    *(float2*)(out + off) = res;
}

// ---------------- launch ----------------
extern "C" void kernel_launch(void* const* d_in, const int* in_sizes, int n_in,
                              void* d_out, int out_size) {
    const float* x   = (const float*)d_in[0];
    const int* edge0 = (const int*)d_in[1];
    const int* edge1 = (const int*)d_in[2];
    const float* W0q = (const float*)d_in[3];
    const float* W0k = (const float*)d_in[4];
    const float* W0v = (const float*)d_in[5];
    const float* b0q = (const float*)d_in[6];
    const float* b0k = (const float*)d_in[7];
    const float* b0v = (const float*)d_in[8];
    const float* W1q = (const float*)d_in[9];
    const float* W1k = (const float*)d_in[10];
    const float* W1v = (const float*)d_in[11];
    const float* b1q = (const float*)d_in[12];
    const float* b1k = (const float*)d_in[13];
    const float* b1v = (const float*)d_in[14];
    float* out = (float*)d_out;

    int M = in_sizes[0] / D_IN;   // 50000
    int E = in_sizes[1] / 2;      // 400000
    int nb = (M + 255) / 256;
    int eb = (E + 255) / 256;

    static cudaStream_t s2 = nullptr;
    static cudaEvent_t evFork = nullptr, evJoin = nullptr;
    static bool init_done = false;
    if (!init_done) {
        cudaFuncSetAttribute(qkv_gemm_f16<0, 128>,
                             cudaFuncAttributeMaxDynamicSharedMemorySize, 81920);
        cudaFuncSetAttribute(qkv_gemm_f16<1, 64>,
                             cudaFuncAttributeMaxDynamicSharedMemorySize, 61440);
        cudaStreamCreateWithFlags(&s2, cudaStreamNonBlocking);
        cudaEventCreateWithFlags(&evFork, cudaEventDisableTiming);
        cudaEventCreateWithFlags(&evJoin, cudaEventDisableTiming);
        init_done = true;
    }

    cudaEventRecord(evFork, 0);
    cudaStreamWaitEvent(s2, evFork, 0);

    split_x_kernel<<<(M * D_IN + 255) / 256, 256>>>(x, M * D_IN);
    split_w_kernel<<<dim3(64, 18), 256>>>(W0q, W0k, W0v,
                                          W1q, W1k, W1v);
    zero2_kernel<<<dim3(nb, 2), 256, 0, s2>>>(M);

    dim3 g0((M + 127) / 128, 1, 12);
    qkv_gemm_f16<0, 128><<<g0, 256, 81920>>>(b0q, b0k, b0v, M);   // <- profiled slot

    count2_kernel<<<dim3(eb, 2), 256, 0, s2>>>(edge0, edge1, E);
    scanA_kernel<<<dim3(nb, 2), 256, 0, s2>>>(M);
    scanB_kernel<<<1, 256, 0, s2>>>(nb);
    scanC_kernel<<<dim3(nb, 2), 256, 0, s2>>>(M, E);
    scatter2_kernel<<<dim3(eb, 2), 256, 0, s2>>>(edge0, edge1, E);
    cudaEventRecord(evJoin, s2);
    cudaStreamWaitEvent(0, evJoin, 0);

    int ab = (M * 32 + 255) / 256;
    attn0_fused_kernel<<<ab, 256>>>(M);

    dim3 g1((M + 127) / 128, 1, 6);
    qkv_gemm_f16<1, 64><<<g1, 256, 61440>>>(b1q, b1k, b1v, M);

    attn1_fused_kernel<<<ab, 256>>>(out, M);
}

// round 16
// speedup vs baseline: 1.0442x; 1.0256x over previous
#include <cuda_runtime.h>
#include <cuda_fp16.h>
#include <math.h>
#include <stdint.h>

#define NN 50000
#define EE 400000
#define D_IN 128
#define D_HID 128
#define D_OUT 64

// ---------------- scratch ----------------
__device__ float g_Q0[4][NN * D_HID];
// interleaved K/V per node: 256 halves/node, group g of 4 dims: [k(4g..4g+3), v(4g..4g+3)]
__device__ __half g_KV0[4][NN * 256];
__device__ float g_H[NN * D_HID];
__device__ float g_Q1[2][NN * D_OUT];
// interleaved layer-1 K/V: 128 halves/node, group g of 2 dims: [k(2g..2g+1), v(2g..2g+1)]
__device__ __half g_KV1[2][NN * 128];
__device__ int g_deg[2][NN];
__device__ int g_scan[2][NN];
__device__ int g_bsum[2][256];
__device__ int g_boff[2][256];
__device__ int g_cursor[2][NN];
__device__ int g_rowptr[2][NN + 1];
__device__ int g_cols[2][EE];

// split-fp16 operands (hi + lo), weights stored transposed [n][k]
__device__ __half g_Xh[NN * D_IN], g_Xl[NN * D_IN];
__device__ __half g_Hh[NN * D_HID], g_Hl[NN * D_HID];
__device__ __half g_W0h[12][D_HID * D_IN], g_W0l[12][D_HID * D_IN];
__device__ __half g_W1h[6][D_OUT * D_HID], g_W1l[6][D_OUT * D_HID];

__device__ __forceinline__ void split_fp16(float v, __half& h, __half& l) {
    h = __float2half_rn(v);
    l = __float2half_rn(v - __half2float(h));
}

// ---------------- CSR build ----------------
__global__ void zero2_kernel(int n) {
    int i = blockIdx.x * blockDim.x + threadIdx.x;
    if (i < n) g_deg[blockIdx.y][i] = 0;
}

__global__ void count2_kernel(const int* __restrict__ e0, const int* __restrict__ e1, int e) {
    int i = blockIdx.x * blockDim.x + threadIdx.x;
    int hop = blockIdx.y;
    const int* rows = hop ? e1 : e0;
    if (i < e) atomicAdd(&g_deg[hop][rows[i]], 1);
}

__global__ void scanA_kernel(int n) {
    int hop = blockIdx.y;
    int chunk = blockIdx.x;
    int tid = threadIdx.x;
    int i = chunk * 256 + tid;
    int v = (i < n) ? g_deg[hop][i] : 0;
    __shared__ int sm[256];
    sm[tid] = v;
    __syncthreads();
#pragma unroll
    for (int off = 1; off < 256; off <<= 1) {
        int t = (tid >= off) ? sm[tid - off] : 0;
        __syncthreads();
        sm[tid] += t;
        __syncthreads();
    }
    if (i < n) g_scan[hop][i] = sm[tid] - v;
    if (tid == 255) g_bsum[hop][chunk] = sm[255];
}

__global__ void scanB_kernel(int nblk) {
    __shared__ int sm[256];
    int tid = threadIdx.x;
    for (int hop = 0; hop < 2; hop++) {
        int v = (tid < nblk) ? g_bsum[hop][tid] : 0;
        sm[tid] = v;
        __syncthreads();
#pragma unroll
        for (int off = 1; off < 256; off <<= 1) {
            int t = (tid >= off) ? sm[tid - off] : 0;
            __syncthreads();
            sm[tid] += t;
            __syncthreads();
        }
        if (tid < nblk) g_boff[hop][tid] = sm[tid] - v;
        __syncthreads();
    }
}

__global__ void scanC_kernel(int n, int e) {
    int i = blockIdx.x * blockDim.x + threadIdx.x;
    int hop = blockIdx.y;
    if (i < n) {
        int rp = g_scan[hop][i] + g_boff[hop][i >> 8];
        g_rowptr[hop][i] = rp;
        g_cursor[hop][i] = rp;
        if (i == 0) g_rowptr[hop][n] = e;
    }
}

__global__ void scatter2_kernel(const int* __restrict__ e0, const int* __restrict__ e1, int e) {
    int i = blockIdx.x * blockDim.x + threadIdx.x;
    int hop = blockIdx.y;
    const int* rows = hop ? e1 : e0;
    if (i < e) {
        int r = rows[i];
        int c = rows[i + e];
        int p = atomicAdd(&g_cursor[hop][r], 1);
        g_cols[hop][p] = c;
    }
}

// ---------------- split precompute ----------------
__global__ void split_x_kernel(const float* __restrict__ x, int n) {
    int i = blockIdx.x * blockDim.x + threadIdx.x;
    if (i < n) split_fp16(x[i], g_Xh[i], g_Xl[i]);
}

__global__ void split_w_kernel(
    const float* __restrict__ W0q, const float* __restrict__ W0k, const float* __restrict__ W0v,
    const float* __restrict__ W1q, const float* __restrict__ W1k, const float* __restrict__ W1v) {
    int z = blockIdx.y;
    int i = blockIdx.x * blockDim.x + threadIdx.x;
    if (z < 12) {
        int c = z / 3, mm = z % 3;
        const float* W = (mm == 0 ? W0q : (mm == 1 ? W0k : W0v)) + (size_t)c * D_IN * D_HID;
        if (i < D_IN * D_HID) {
            int k = i / D_HID, n = i % D_HID;
            split_fp16(W[i], g_W0h[z][n * D_IN + k], g_W0l[z][n * D_IN + k]);
        }
    } else {
        int zz = z - 12;
        int c = zz / 3, mm = zz % 3;
        const float* W = (mm == 0 ? W1q : (mm == 1 ? W1k : W1v)) + (size_t)c * D_HID * D_OUT;
        if (i < D_HID * D_OUT) {
            int k = i / D_OUT, n = i % D_OUT;
            split_fp16(W[i], g_W1h[zz][n * D_HID + k], g_W1l[zz][n * D_HID + k]);
        }
    }
}

// ---------------- split-fp16 tensor-core GEMM: cp.async double-buffer + ldmatrix ------
// Q (mm==0): 3-term fp16 split, fp32 output.  K/V (mm!=0): 1 term, interleaved fp16 out.
__device__ __forceinline__ void mma_f16(float* c, const uint32_t* a, const uint32_t* b) {
    asm volatile(
        "mma.sync.aligned.m16n8k16.row.col.f32.f16.f16.f32 "
        "{%0,%1,%2,%3}, {%4,%5,%6,%7}, {%8,%9}, {%0,%1,%2,%3};"
        : "+f"(c[0]), "+f"(c[1]), "+f"(c[2]), "+f"(c[3])
        : "r"(a[0]), "r"(a[1]), "r"(a[2]), "r"(a[3]), "r"(b[0]), "r"(b[1]));
}

__device__ __forceinline__ void ldsm_x4(uint32_t* r, uint32_t addr) {
    asm volatile("ldmatrix.sync.aligned.m8n8.x4.shared.b16 {%0,%1,%2,%3}, [%4];"
                 : "=r"(r[0]), "=r"(r[1]), "=r"(r[2]), "=r"(r[3]) : "r"(addr));
}

__device__ __forceinline__ void cp_async16(uint32_t dst, const void* src, bool valid) {
    int sz = valid ? 16 : 0;
    asm volatile("cp.async.cg.shared.global [%0], [%1], 16, %2;"
                 :: "r"(dst), "l"(src), "r"(sz));
}
__device__ __forceinline__ void cp_commit() {
    asm volatile("cp.async.commit_group;");
}
__device__ __forceinline__ void cp_wait0() {
    asm volatile("cp.async.wait_group 0;" ::: "memory");
}

// BM=128, BK=32, 256 threads = 8 warps (2M x 4N). 2-stage cp.async pipeline.
template <int LAYER, int BN>
__global__ void __launch_bounds__(256) qkv_gemm_f16(
    const float* __restrict__ bq, const float* __restrict__ bk, const float* __restrict__ bv,
    int M) {
    constexpr int KD = 128;
    constexpr int BM = 128;
    constexpr int BK = 32;
    constexpr int MT = 4;
    constexpr int NT = BN / 32;
    constexpr int NP = NT / 2;
    constexpr int WNT = BN / 4;
    constexpr int ST = BK + 8;
    constexpr int NIT = KD / BK;
    constexpr uint32_t A_BYTES = BM * ST * 2;
    constexpr uint32_t B_BYTES = BN * ST * 2;
    constexpr uint32_t OFF_AL = 2 * A_BYTES;
    constexpr uint32_t OFF_BH = 4 * A_BYTES;
    constexpr uint32_t OFF_BL = 4 * A_BYTES + 2 * B_BYTES;

    extern __shared__ char smem[];
    uint32_t sb = (uint32_t)__cvta_generic_to_shared(smem);

    int z = blockIdx.z;
    int c = z / 3, mm = z % 3;
    const bool full = (mm == 0);
    const __half *Ah_g, *Al_g, *Bh_g, *Bl_g;
    if (LAYER == 0) { Ah_g = g_Xh; Al_g = g_Xl; Bh_g = g_W0h[z]; Bl_g = g_W0l[z]; }
    else            { Ah_g = g_Hh; Al_g = g_Hl; Bh_g = g_W1h[z]; Bl_g = g_W1l[z]; }
    const float* bias = (mm == 0 ? bq : (mm == 1 ? bk : bv)) + (size_t)c * BN;
    float* Of = nullptr;
    __half* Okv = nullptr;   // interleaved K/V target
    if (LAYER == 0) {
        if (mm == 0) Of = g_Q0[c];
        else Okv = g_KV0[c];
    } else {
        if (mm == 0) Of = g_Q1[c];
        else Okv = g_KV1[c];
    }
    const int kvoff = (mm == 2) ? (LAYER == 0 ? 4 : 2) : 0;  // V goes in second half of group

    int tid = threadIdx.x;
    int warp = tid >> 5;
    int lane = tid & 31;
    int gid = lane >> 2;
    int tig = lane & 3;
    int wm = warp >> 2;
    int wn = warp & 3;
    int row0 = blockIdx.x * BM;
    int m0w = wm * 64;
    int n0w = wn * WNT;

    int mat = lane >> 3;
    int mrow = lane & 7;

    uint32_t aAddrH[MT], aAddrL[MT];
#pragma unroll
    for (int mt = 0; mt < MT; mt++) {
        int row = m0w + mt * 16 + ((mat & 1) << 3) + mrow;
        int col = (mat >> 1) << 3;
        uint32_t o = (row * ST + col) * 2;
        aAddrH[mt] = sb + o;
        aAddrL[mt] = sb + OFF_AL + o;
    }
    uint32_t bAddrH[NP], bAddrL[NP];
#pragma unroll
    for (int p = 0; p < NP; p++) {
        int row = n0w + p * 16 + ((mat >> 1) << 3) + mrow;
        int col = (mat & 1) << 3;
        uint32_t o = (row * ST + col) * 2;
        bAddrH[p] = sb + OFF_BH + o;
        bAddrL[p] = sb + OFF_BL + o;
    }

    float acc[MT][NT][4];
#pragma unroll
    for (int i = 0; i < MT; i++)
#pragma unroll
        for (int j = 0; j < NT; j++)
#pragma unroll
            for (int t = 0; t < 4; t++) acc[i][j][t] = 0.f;

    auto issue = [&](int it) {
        int st = it & 1;
        int k0 = it * BK;
        uint32_t aB = sb + st * A_BYTES;
        uint32_t aBl = sb + OFF_AL + st * A_BYTES;
#pragma unroll
        for (int f = tid; f < BM * BK / 8; f += 256) {
            int r = f >> 2, kc = (f & 3) * 8;
            int gr = row0 + r;
            bool v = gr < M;
            int gs = v ? gr : 0;
            uint32_t o = (r * ST + kc) * 2;
            cp_async16(aB + o, Ah_g + (size_t)gs * KD + k0 + kc, v);
            if (full)
                cp_async16(aBl + o, Al_g + (size_t)gs * KD + k0 + kc, v);
        }
        uint32_t bB = sb + OFF_BH + st * B_BYTES;
        uint32_t bBl = sb + OFF_BL + st * B_BYTES;
#pragma unroll
        for (int f = tid; f < BN * BK / 8; f += 256) {
            int r = f >> 2, kc = (f & 3) * 8;
            uint32_t o = (r * ST + kc) * 2;
            cp_async16(bB + o, Bh_g + (size_t)r * KD + k0 + kc, true);
            if (full)
                cp_async16(bBl + o, Bl_g + (size_t)r * KD + k0 + kc, true);
        }
        cp_commit();
    };

    issue(0);

#pragma unroll
    for (int it = 0; it < NIT; it++) {
        cp_wait0();
        __syncthreads();
        if (it + 1 < NIT) issue(it + 1);
        uint32_t aoff = (uint32_t)(it & 1) * A_BYTES;
        uint32_t boff = (uint32_t)(it & 1) * B_BYTES;
#pragma unroll
        for (int s = 0; s < 2; s++) {
            uint32_t soff = s * 16 * 2;
            uint32_t bhr[NP][4], blr[NP][4];
#pragma unroll
            for (int p = 0; p < NP; p++) {
                ldsm_x4(bhr[p], bAddrH[p] + boff + soff);
                if (full) ldsm_x4(blr[p], bAddrL[p] + boff + soff);
            }
#pragma unroll
            for (int mt = 0; mt < MT; mt++) {
                uint32_t ah[4], al[4];
                ldsm_x4(ah, aAddrH[mt] + aoff + soff);
                if (full) ldsm_x4(al, aAddrL[mt] + aoff + soff);
#pragma unroll
                for (int nt = 0; nt < NT; nt++) {
                    const uint32_t* bh2 = &bhr[nt >> 1][(nt & 1) * 2];
                    mma_f16(acc[mt][nt], ah, bh2);
                    if (full) {
                        const uint32_t* bl2 = &blr[nt >> 1][(nt & 1) * 2];
                        mma_f16(acc[mt][nt], ah, bl2);
                        mma_f16(acc[mt][nt], al, bh2);
                    }
                }
            }
        }
    }

#pragma unroll
    for (int mt = 0; mt < MT; mt++) {
        int r0 = row0 + m0w + mt * 16 + gid;
        int r1 = r0 + 8;
#pragma unroll
        for (int nt = 0; nt < NT; nt++) {
            int col = n0w + nt * 8 + 2 * tig;
            float bx = bias[col], by = bias[col + 1];
            if (mm == 0) {
                if (r0 < M)
                    *(float2*)(Of + (size_t)r0 * BN + col) =
                        make_float2(acc[mt][nt][0] + bx, acc[mt][nt][1] + by);
                if (r1 < M)
                    *(float2*)(Of + (size_t)r1 * BN + col) =
                        make_float2(acc[mt][nt][2] + bx, acc[mt][nt][3] + by);
            } else {
                // interleaved: D=128 -> group col/4 size 8; D=64 -> group col/2 size 4
                // col = even (2*tig), pair (col, col+1) within one group for both layouts
                int gbase;
                if (LAYER == 0) gbase = (col >> 2) * 8 + (col & 3) + kvoff;
                else            gbase = (col >> 1) * 4 + kvoff;
                if (r0 < M) {
                    __half2 h = __floats2half2_rn(acc[mt][nt][0] + bx, acc[mt][nt][1] + by);
                    *(__half2*)(Okv + (size_t)r0 * (LAYER == 0 ? 256 : 128) + gbase) = h;
                }
                if (r1 < M) {
                    __half2 h = __floats2half2_rn(acc[mt][nt][2] + bx, acc[mt][nt][3] + by);
                    *(__half2*)(Okv + (size_t)r1 * (LAYER == 0 ? 256 : 128) + gbase) = h;
                }
            }
        }
    }
}

// ---------------- layer-0 fused attention: interleaved KV, one uint4 per combo/edge --
__global__ void attn0_fused_kernel(int n) {
    int gw = (blockIdx.x * blockDim.x + threadIdx.x) >> 5;
    if (gw >= n) return;
    int lane = threadIdx.x & 31;
    const float scale = 0.17677669529663687f;  // 1/sqrt(32)
    size_t off = (size_t)gw * 128 + lane * 4;
    size_t kvl = (size_t)lane * 8;

    float4 y = make_float4(0.f, 0.f, 0.f, 0.f);

#pragma unroll
    for (int hop = 0; hop < 2; hop++) {
        int cA = hop;
        int cB = hop + 2;
        float beta = hop ? 0.25f : 1.0f;
        const float* __restrict__ QA = g_Q0[cA];
        const __half* __restrict__ KVA = g_KV0[cA];
        const float* __restrict__ QB = g_Q0[cB];
        const __half* __restrict__ KVB = g_KV0[cB];
        const int* __restrict__ cols = g_cols[hop];

        float4 qa = *(const float4*)(QA + off);
        float4 qb = *(const float4*)(QB + off);
        float4 aA = make_float4(0.f, 0.f, 0.f, 0.f);
        float4 aB = make_float4(0.f, 0.f, 0.f, 0.f);
        float mA = -INFINITY, lA = 0.f, mB = -INFINITY, lB = 0.f;

        int s0 = g_rowptr[hop][gw], s1 = g_rowptr[hop][gw + 1];
        uint4 kvaN, kvbN;
        if (s0 < s1) {
            size_t co = (size_t)cols[s0] * 256 + kvl;
            kvaN = *(const uint4*)(KVA + co);
            kvbN = *(const uint4*)(KVB + co);
        }
        for (int p = s0; p < s1; p++) {
            uint4 kva = kvaN, kvb = kvbN;
            if (p + 1 < s1) {
                size_t co = (size_t)cols[p + 1] * 256 + kvl;
                kvaN = *(const uint4*)(KVA + co);
                kvbN = *(const uint4*)(KVB + co);
            }
            float2 ka01 = __half22float2(*(__half2*)&kva.x);
            float2 ka23 = __half22float2(*(__half2*)&kva.y);
            float2 kb01 = __half22float2(*(__half2*)&kvb.x);
            float2 kb23 = __half22float2(*(__half2*)&kvb.y);
            float dA = qa.x * ka01.x + qa.y * ka01.y + qa.z * ka23.x + qa.w * ka23.y;
            float dB = qb.x * kb01.x + qb.y * kb01.y + qb.z * kb23.x + qb.w * kb23.y;
            dA += __shfl_xor_sync(0xffffffffu, dA, 1);
            dA += __shfl_xor_sync(0xffffffffu, dA, 2);
            dA += __shfl_xor_sync(0xffffffffu, dA, 4);
            dB += __shfl_xor_sync(0xffffffffu, dB, 1);
            dB += __shfl_xor_sync(0xffffffffu, dB, 2);
            dB += __shfl_xor_sync(0xffffffffu, dB, 4);
            float2 va01 = __half22float2(*(__half2*)&kva.z);
            float2 va23 = __half22float2(*(__half2*)&kva.w);
            float2 vb01 = __half22float2(*(__half2*)&kvb.z);
            float2 vb23 = __half22float2(*(__half2*)&kvb.w);
            {
                float s = dA * scale;
                float nm = fmaxf(mA, s);
                float sc = __expf(mA - nm);
                float pe = __expf(s - nm);
                lA = lA * sc + pe;
                aA.x = aA.x * sc + pe * va01.x; aA.y = aA.y * sc + pe * va01.y;
                aA.z = aA.z * sc + pe * va23.x; aA.w = aA.w * sc + pe * va23.y;
                mA = nm;
            }
            {
                float s = dB * scale;
                float nm = fmaxf(mB, s);
                float sc = __expf(mB - nm);
                float pe = __expf(s - nm);
                lB = lB * sc + pe;
                aB.x = aB.x * sc + pe * vb01.x; aB.y = aB.y * sc + pe * vb01.y;
                aB.z = aB.z * sc + pe * vb23.x; aB.w = aB.w * sc + pe * vb23.y;
                mB = nm;
            }
        }
        float wA = beta / (lA + 1e-16f);
        float wB = beta / (lB + 1e-16f);
        y.x += aA.x * wA + aB.x * wB;
        y.y += aA.y * wA + aB.y * wB;
        y.z += aA.z * wA + aB.z * wB;
        y.w += aA.w * wA + aB.w * wB;
    }

    y.x = y.x > 0.f ? y.x : expm1f(y.x);
    y.y = y.y > 0.f ? y.y : expm1f(y.y);
    y.z = y.z > 0.f ? y.z : expm1f(y.z);
    y.w = y.w > 0.f ? y.w : expm1f(y.w);
    *(float4*)(g_H + off) = y;
    float vals[4] = {y.x, y.y, y.z, y.w};
#pragma unroll
    for (int t = 0; t < 4; t++) split_fp16(vals[t], g_Hh[off + t], g_Hl[off + t]);
}

// ---------------- layer-1 fused attention: interleaved KV, one uint2 per edge --------
__global__ void attn1_fused_kernel(float* __restrict__ out, int n) {
    int gw = (blockIdx.x * blockDim.x + threadIdx.x) >> 5;
    if (gw >= n) return;
    int lane = threadIdx.x & 31;
    const float scale = 0.25f;  // 1/sqrt(16)
    size_t off = (size_t)gw * 64 + lane * 2;
    size_t kvl = (size_t)lane * 4;

    float2 res = make_float2(0.f, 0.f);
#pragma unroll
    for (int combo = 0; combo < 2; combo++) {
        const float* __restrict__ Q = g_Q1[combo];
        const __half* __restrict__ KV = g_KV1[combo];
        const int* __restrict__ cols = g_cols[combo];
        float beta = (combo == 0) ? 1.0f : 0.25f;

        float2 q = *(const float2*)(Q + off);
        float2 acc = make_float2(0.f, 0.f);
        float m = -INFINITY, l = 0.f;

        int s0 = g_rowptr[combo][gw], s1 = g_rowptr[combo][gw + 1];
        uint2 kvN;
        if (s0 < s1) {
            size_t co = (size_t)cols[s0] * 128 + kvl;
            kvN = *(const uint2*)(KV + co);
        }
        for (int p = s0; p < s1; p++) {
            uint2 kv = kvN;
            if (p + 1 < s1) {
                size_t co = (size_t)cols[p + 1] * 128 + kvl;
                kvN = *(const uint2*)(KV + co);
            }
            float2 k = __half22float2(*(__half2*)&kv.x);
            float d = q.x * k.x + q.y * k.y;
            d += __shfl_xor_sync(0xffffffffu, d, 1);
            d += __shfl_xor_sync(0xffffffffu, d, 2);
            d += __shfl_xor_sync(0xffffffffu, d, 4);
            float2 v = __half22float2(*(__half2*)&kv.y);
            float s = d * scale;
            float nm = fmaxf(m, s);
            float sc = __expf(m - nm);
            float pe = __expf(s - nm);
            l = l * sc + pe;
            acc.x = acc.x * sc + pe * v.x;
            acc.y = acc.y * sc + pe * v.y;
            m = nm;
        }
        float w = beta / (l + 1e-16f);
        res.x += acc.x * w;
        res.y += acc.y * w;
    }

    float mx = fmaxf(res.x, res.y);
#pragma unroll
    for (int o = 16; o; o >>= 1) mx = fmaxf(mx, __shfl_xor_sync(0xffffffffu, mx, o));
    float s = expf(res.x - mx) + expf(res.y - mx);
#pragma unroll
    for (int o = 16; o; o >>= 1) s += __shfl_xor_sync(0xffffffffu, s, o);
    float lg = mx + logf(s);
    res.x -= lg; res.y -= lg;
    *(float2*)(out + off) = res;
}

// ---------------- launch ----------------
extern "C" void kernel_launch(void* const* d_in, const int* in_sizes, int n_in,
                              void* d_out, int out_size) {
    const float* x   = (const float*)d_in[0];
    const int* edge0 = (const int*)d_in[1];
    const int* edge1 = (const int*)d_in[2];
    const float* W0q = (const float*)d_in[3];
    const float* W0k = (const float*)d_in[4];
    const float* W0v = (const float*)d_in[5];
    const float* b0q = (const float*)d_in[6];
    const float* b0k = (const float*)d_in[7];
    const float* b0v = (const float*)d_in[8];
    const float* W1q = (const float*)d_in[9];
    const float* W1k = (const float*)d_in[10];
    const float* W1v = (const float*)d_in[11];
    const float* b1q = (const float*)d_in[12];
    const float* b1k = (const float*)d_in[13];
    const float* b1v = (const float*)d_in[14];
    float* out = (float*)d_out;

    int M = in_sizes[0] / D_IN;   // 50000
    int E = in_sizes[1] / 2;      // 400000
    int nb = (M + 255) / 256;
    int eb = (E + 255) / 256;

    static cudaStream_t s2 = nullptr;
    static cudaEvent_t evFork = nullptr, evJoin = nullptr;
    static bool init_done = false;
    if (!init_done) {
        cudaFuncSetAttribute(qkv_gemm_f16<0, 128>,
                             cudaFuncAttributeMaxDynamicSharedMemorySize, 81920);
        cudaFuncSetAttribute(qkv_gemm_f16<1, 64>,
                             cudaFuncAttributeMaxDynamicSharedMemorySize, 61440);
        cudaStreamCreateWithFlags(&s2, cudaStreamNonBlocking);
        cudaEventCreateWithFlags(&evFork, cudaEventDisableTiming);
        cudaEventCreateWithFlags(&evJoin, cudaEventDisableTiming);
        init_done = true;
    }

    cudaEventRecord(evFork, 0);
    cudaStreamWaitEvent(s2, evFork, 0);

    split_x_kernel<<<(M * D_IN + 255) / 256, 256>>>(x, M * D_IN);
    split_w_kernel<<<dim3(64, 18), 256>>>(W0q, W0k, W0v,
                                          W1q, W1k, W1v);
    zero2_kernel<<<dim3(nb, 2), 256, 0, s2>>>(M);

    dim3 g0((M + 127) / 128, 1, 12);
    qkv_gemm_f16<0, 128><<<g0, 256, 81920>>>(b0q, b0k, b0v, M);   // <- profiled slot

    count2_kernel<<<dim3(eb, 2), 256, 0, s2>>>(edge0, edge1, E);
    scanA_kernel<<<dim3(nb, 2), 256, 0, s2>>>(M);
    scanB_kernel<<<1, 256, 0, s2>>>(nb);
    scanC_kernel<<<dim3(nb, 2), 256, 0, s2>>>(M, E);
    scatter2_kernel<<<dim3(eb, 2), 256, 0, s2>>>(edge0, edge1, E);
    cudaEventRecord(evJoin, s2);
    cudaStreamWaitEvent(0, evJoin, 0);

    int ab = (M * 32 + 255) / 256;
    attn0_fused_kernel<<<ab, 256>>>(M);

    dim3 g1((M + 127) / 128, 1, 6);
    qkv_gemm_f16<1, 64><<<g1, 256, 61440>>>(b1q, b1k, b1v, M);

    attn1_fused_kernel<<<ab, 256>>>(out, M);
}